// round 14
// baseline (speedup 1.0000x reference)
#include <cuda_runtime.h>
#include <math.h>

// Problem constants: B=4, N=1024, D=512, H=8, dh=64
#define NB 4
#define NN 1024
#define ND 512
#define NH 8
#define FDIM 144   // phase1 [0,72): lor features (65 used), phase2 [72,144): kin features (66 used)

// ---- static scratch (no allocations allowed) ----
__device__ float g_xqkv[4096 * 1536];          // qkv(x_tan)
__device__ float g_vqkv[4096 * 1024];          // q,k parts of qkv(v_tan)
__device__ float g_Fq[32 * 1024 * FDIM];       // query-side fused features, n-major
__device__ float g_Fk[32 * 1024 * FDIM];       // key-side fused features
__device__ unsigned g_b1[1024 * 32];           // (A>0) bitset rows
__device__ unsigned g_b2[1024 * 32];           // (A^2>0)
__device__ unsigned g_b3[1024 * 32];           // (A^3>0)

// ---------------- topo bit kernels ----------------
__global__ void pack_kernel(const float* __restrict__ A) {
    int i = blockIdx.x, w = threadIdx.x;
    const float* row = A + (size_t)i * 1024 + w * 32;
    unsigned word = 0;
#pragma unroll
    for (int b = 0; b < 32; b++)
        if (row[b] > 0.f) word |= (1u << b);
    g_b1[i * 32 + w] = word;
}

// dst row i = OR over {k : src[i][k]=1} of g_b1 row k   (A^{p+1}>0 from A^p>0)
__global__ void pow2_kernel() {
    int i = blockIdx.x, w = threadIdx.x;
    unsigned acc = 0;
    for (int kw = 0; kw < 32; kw++) {
        unsigned word = g_b1[i * 32 + kw];
        while (word) {
            int b = __ffs(word) - 1; word &= word - 1;
            acc |= g_b1[(kw * 32 + b) * 32 + w];
        }
    }
    g_b2[i * 32 + w] = acc;
}
__global__ void pow3_kernel() {
    int i = blockIdx.x, w = threadIdx.x;
    unsigned acc = 0;
    for (int kw = 0; kw < 32; kw++) {
        unsigned word = g_b2[i * 32 + kw];
        while (word) {
            int b = __ffs(word) - 1; word &= word - 1;
            acc |= g_b1[(kw * 32 + b) * 32 + w];
        }
    }
    g_b3[i * 32 + w] = acc;
}

// ---------------- shared GEMM micro-kernel ----------------
// 128x64 tile, 8x4 micro, KT=8, double-buffered smem (1 barrier/chunk).
#define INNER8x4(ACC, ASB, BSB)                                                \
    _Pragma("unroll")                                                          \
    for (int kk = 0; kk < 8; kk++) {                                           \
        float4 a0 = *(const float4*)&ASB[kk][ty * 8];                          \
        float4 a1 = *(const float4*)&ASB[kk][ty * 8 + 4];                      \
        float4 bv = *(const float4*)&BSB[kk][tx * 4];                          \
        float ar[8] = {a0.x, a0.y, a0.z, a0.w, a1.x, a1.y, a1.z, a1.w};        \
        float br[4] = {bv.x, bv.y, bv.z, bv.w};                                \
        _Pragma("unroll") for (int ii = 0; ii < 8; ii++)                       \
            _Pragma("unroll") for (int jj = 0; jj < 4; jj++)                   \
                ACC[ii][jj] += ar[ii] * br[jj];                                \
    }

// ---------------- fp32 NT GEMM: C[m][n] = sum_k A[m][k]*B[n][k] + bias[n] ----------------
__global__ __launch_bounds__(256) void gemm_nt(
    const float* __restrict__ A, const float* __restrict__ Bm,
    const float* __restrict__ bias, float* __restrict__ C, int K, int ldc) {
    __shared__ float As[2][8][128];
    __shared__ float Bs[2][8][64];
    int m0 = blockIdx.y * 128, n0 = blockIdx.x * 64;
    int t = threadIdx.x;
    int am = t >> 1, af = (t & 1) * 4;
    int bm = t >> 2, bf = (t & 3) * 2;
    int ty = t >> 4, tx = t & 15;
    const float* Ap = A + (size_t)(m0 + am) * K + af;
    const float* Bp = Bm + (size_t)(n0 + bm) * K + bf;
    float4 pa = *(const float4*)Ap;
    float2 pb = *(const float2*)Bp;
    float acc[8][4];
#pragma unroll
    for (int ii = 0; ii < 8; ii++)
#pragma unroll
        for (int jj = 0; jj < 4; jj++) acc[ii][jj] = 0.f;
    int nc = K >> 3;
    // prologue: stage chunk 0 into buffer 0
    As[0][af][am] = pa.x; As[0][af + 1][am] = pa.y; As[0][af + 2][am] = pa.z; As[0][af + 3][am] = pa.w;
    Bs[0][bf][bm] = pb.x; Bs[0][bf + 1][bm] = pb.y;
    __syncthreads();
    for (int c = 0; c < nc; c++) {
        int cur = c & 1, nxt = cur ^ 1;
        if (c + 1 < nc) {
            pa = *(const float4*)(Ap + (c + 1) * 8);
            pb = *(const float2*)(Bp + (c + 1) * 8);
        }
        INNER8x4(acc, As[cur], Bs[cur])
        if (c + 1 < nc) {
            As[nxt][af][am] = pa.x; As[nxt][af + 1][am] = pa.y;
            As[nxt][af + 2][am] = pa.z; As[nxt][af + 3][am] = pa.w;
            Bs[nxt][bf][bm] = pb.x; Bs[nxt][bf + 1][bm] = pb.y;
            __syncthreads();
        }
    }
#pragma unroll
    for (int ii = 0; ii < 8; ii++) {
        int m = m0 + ty * 8 + ii;
#pragma unroll
        for (int jj = 0; jj < 4; jj++) {
            int n = n0 + tx * 4 + jj;
            C[(size_t)m * ldc + n] = acc[ii][jj] + bias[n];
        }
    }
}

// ---------------- feature prep: one warp per (b,h,n) ----------------
__global__ __launch_bounds__(256) void prep_kernel() {
    int gw = blockIdx.x * 8 + (threadIdx.x >> 5);
    int lane = threadIdx.x & 31;
    int n = gw & 1023;
    int bh = gw >> 10;
    int b = bh >> 3, h = bh & 7;
    const float* xrow = g_xqkv + (size_t)(b * 1024 + n) * 1536;
    const float* vrow = g_vqkv + (size_t)(b * 1024 + n) * 1024;
    float* fq = g_Fq + (size_t)(bh * 1024 + n) * FDIM;
    float* fk = g_Fk + (size_t)(bh * 1024 + n) * FDIM;

    // --- q embed (phase1 features) ---
    {
        float qa = xrow[h * 64 + lane], qb = xrow[h * 64 + 32 + lane];
        float ss = qa * qa + qb * qb;
#pragma unroll
        for (int o = 16; o; o >>= 1) ss += __shfl_xor_sync(0xffffffffu, ss, o);
        float norm = sqrtf(fmaxf(ss, 1e-7f));
        float s = fminf(3.0f / norm, 1.0f);
        float m = sqrtf(fmaxf(ss * s * s, 1e-14f));
        float sc = sinhf(m) / m * s;
        if (lane == 0) fq[0] = -coshf(m);      // sign folded: lor = sum(feat_q*feat_k)
        fq[1 + lane] = sc * qa;
        fq[33 + lane] = sc * qb;
        if (lane < 7) fq[65 + lane] = 0.f;
    }
    // --- k embed ---
    {
        float ka = xrow[512 + h * 64 + lane], kb = xrow[512 + h * 64 + 32 + lane];
        float ss = ka * ka + kb * kb;
#pragma unroll
        for (int o = 16; o; o >>= 1) ss += __shfl_xor_sync(0xffffffffu, ss, o);
        float norm = sqrtf(fmaxf(ss, 1e-7f));
        float s = fminf(3.0f / norm, 1.0f);
        float m = sqrtf(fmaxf(ss * s * s, 1e-14f));
        float sc = sinhf(m) / m * s;
        if (lane == 0) fk[0] = coshf(m);
        fk[1 + lane] = sc * ka;
        fk[33 + lane] = sc * kb;
        if (lane < 7) fk[65 + lane] = 0.f;
    }
    // --- kin features (phase2): dot(u,w) = vq2 + vk2 - 2 vq.vk ---
    {
        float va = vrow[h * 64 + lane], vb = vrow[h * 64 + 32 + lane];
        float ss = va * va + vb * vb;
#pragma unroll
        for (int o = 16; o; o >>= 1) ss += __shfl_xor_sync(0xffffffffu, ss, o);
        if (lane == 0) { fq[72] = ss; fq[73] = 1.f; }
        fq[74 + lane] = -2.f * va;
        fq[106 + lane] = -2.f * vb;
        if (lane < 6) fq[138 + lane] = 0.f;
    }
    {
        float va = vrow[512 + h * 64 + lane], vb = vrow[512 + h * 64 + 32 + lane];
        float ss = va * va + vb * vb;
#pragma unroll
        for (int o = 16; o; o >>= 1) ss += __shfl_xor_sync(0xffffffffu, ss, o);
        if (lane == 0) { fk[72] = 1.f; fk[73] = ss; }
        fk[74 + lane] = va;
        fk[106 + lane] = vb;
        if (lane < 6) fk[138 + lane] = 0.f;
    }
}

// ---------------- score GEMM + epilogue (writes pre-softmax scores into attn) ----------------
__global__ __launch_bounds__(256) void score_kernel(
    const float* __restrict__ tau, const float* __restrict__ gamma,
    float* __restrict__ attn) {
    int bh = blockIdx.z, h = bh & 7;
    const float* A = g_Fq + (size_t)bh * NN * FDIM;
    const float* Bm = g_Fk + (size_t)bh * NN * FDIM;
    __shared__ float As[2][8][128];
    __shared__ float Bs[2][8][64];
    int i0 = blockIdx.y * 128, j0 = blockIdx.x * 64;
    int t = threadIdx.x;
    int am = t >> 1, af = (t & 1) * 4;
    int bm = t >> 2, bf = (t & 3) * 2;
    int ty = t >> 4, tx = t & 15;
    const float* Ap = A + (size_t)(i0 + am) * FDIM + af;
    const float* Bp = Bm + (size_t)(j0 + bm) * FDIM + bf;
    float4 pa = *(const float4*)Ap;
    float2 pb = *(const float2*)Bp;
    float acc1[8][4], acc2[8][4];
#pragma unroll
    for (int ii = 0; ii < 8; ii++)
#pragma unroll
        for (int jj = 0; jj < 4; jj++) { acc1[ii][jj] = 0.f; acc2[ii][jj] = 0.f; }

    As[0][af][am] = pa.x; As[0][af + 1][am] = pa.y; As[0][af + 2][am] = pa.z; As[0][af + 3][am] = pa.w;
    Bs[0][bf][bm] = pb.x; Bs[0][bf + 1][bm] = pb.y;
    __syncthreads();
    for (int c = 0; c < 18; c++) {
        int cur = c & 1, nxt = cur ^ 1;
        if (c + 1 < 18) {
            pa = *(const float4*)(Ap + (c + 1) * 8);
            pb = *(const float2*)(Bp + (c + 1) * 8);
        }
        if (c < 9) {
            INNER8x4(acc1, As[cur], Bs[cur])
        } else {
            INNER8x4(acc2, As[cur], Bs[cur])
        }
        if (c + 1 < 18) {
            As[nxt][af][am] = pa.x; As[nxt][af + 1][am] = pa.y;
            As[nxt][af + 2][am] = pa.z; As[nxt][af + 3][am] = pa.w;
            Bs[nxt][bf][bm] = pb.x; Bs[nxt][bf + 1][bm] = pb.y;
            __syncthreads();
        }
    }

    float inv_tau = 1.f / fmaxf(tau[h], 1e-3f);
    float g0 = gamma[h * 3 + 0], g1 = gamma[h * 3 + 1], g2 = gamma[h * 3 + 2];
#pragma unroll
    for (int ii = 0; ii < 8; ii++) {
        int i = i0 + ty * 8 + ii;
#pragma unroll
        for (int jj = 0; jj < 4; jj++) {
            int j = j0 + tx * 4 + jj;
            int w = j >> 5, bit = j & 31;
            float st = 0.f;
            if (i != j) {
                st = g0 * (float)((g_b1[i * 32 + w] >> bit) & 1u)
                   + g1 * (float)((g_b2[i * 32 + w] >> bit) & 1u)
                   + g2 * (float)((g_b3[i * 32 + w] >> bit) & 1u);
            }
            float s = (1.f + acc1[ii][jj]) * inv_tau - fmaxf(acc2[ii][jj], 0.f) + st;
            attn[((size_t)bh * NN + i) * NN + j] = s;
        }
    }
}

// ---------------- row softmax (in place on attn) ----------------
__global__ __launch_bounds__(256) void softmax_kernel(float* __restrict__ attn) {
    float* row = attn + (size_t)blockIdx.x * 1024;
    int t = threadIdx.x;
    float4 v = reinterpret_cast<float4*>(row)[t];
    __shared__ float sm[8], ssum[8];
    float m = fmaxf(fmaxf(v.x, v.y), fmaxf(v.z, v.w));
#pragma unroll
    for (int o = 16; o; o >>= 1) m = fmaxf(m, __shfl_xor_sync(0xffffffffu, m, o));
    if ((t & 31) == 0) sm[t >> 5] = m;
    __syncthreads();
    float mx = fmaxf(fmaxf(fmaxf(sm[0], sm[1]), fmaxf(sm[2], sm[3])),
                     fmaxf(fmaxf(sm[4], sm[5]), fmaxf(sm[6], sm[7])));
    float e0 = expf(v.x - mx), e1 = expf(v.y - mx), e2 = expf(v.z - mx), e3 = expf(v.w - mx);
    float s = e0 + e1 + e2 + e3;
#pragma unroll
    for (int o = 16; o; o >>= 1) s += __shfl_xor_sync(0xffffffffu, s, o);
    if ((t & 31) == 0) ssum[t >> 5] = s;
    __syncthreads();
    float tot = ssum[0] + ssum[1] + ssum[2] + ssum[3] + ssum[4] + ssum[5] + ssum[6] + ssum[7];
    float inv = 1.f / tot;
    reinterpret_cast<float4*>(row)[t] = make_float4(e0 * inv, e1 * inv, e2 * inv, e3 * inv);
}

// ---------------- z = attn @ v_s, written strided into z_tan ----------------
__global__ __launch_bounds__(256) void zgemm_kernel(
    const float* __restrict__ attn, float* __restrict__ out) {
    int bh = blockIdx.z, b = bh >> 3, h = bh & 7;
    const float* A = attn + (size_t)bh * NN * NN;
    __shared__ float As[2][8][128];
    __shared__ float Bs[2][8][64];
    int i0 = blockIdx.y * 128;
    int t = threadIdx.x;
    int am = t >> 1, af = (t & 1) * 4;
    int d = t & 63, kq = t >> 6;  // 0..3
    int ty = t >> 4, tx = t & 15;
    const float* Ap = A + (size_t)(i0 + am) * NN + af;
    const float* Vp = g_xqkv + (size_t)(b * 1024) * 1536 + 1024 + h * 64 + d;
    float4 pa = *(const float4*)Ap;
    float pb0 = Vp[(size_t)kq * 1536];
    float pb1 = Vp[(size_t)(kq + 4) * 1536];
    float acc[8][4];
#pragma unroll
    for (int ii = 0; ii < 8; ii++)
#pragma unroll
        for (int jj = 0; jj < 4; jj++) acc[ii][jj] = 0.f;
    As[0][af][am] = pa.x; As[0][af + 1][am] = pa.y; As[0][af + 2][am] = pa.z; As[0][af + 3][am] = pa.w;
    Bs[0][kq][d] = pb0; Bs[0][kq + 4][d] = pb1;
    __syncthreads();
    for (int c = 0; c < 128; c++) {
        int cur = c & 1, nxt = cur ^ 1;
        if (c + 1 < 128) {
            pa = *(const float4*)(Ap + (c + 1) * 8);
            pb0 = Vp[(size_t)((c + 1) * 8 + kq) * 1536];
            pb1 = Vp[(size_t)((c + 1) * 8 + kq + 4) * 1536];
        }
        INNER8x4(acc, As[cur], Bs[cur])
        if (c + 1 < 128) {
            As[nxt][af][am] = pa.x; As[nxt][af + 1][am] = pa.y;
            As[nxt][af + 2][am] = pa.z; As[nxt][af + 3][am] = pa.w;
            Bs[nxt][kq][d] = pb0; Bs[nxt][kq + 4][d] = pb1;
            __syncthreads();
        }
    }
#pragma unroll
    for (int ii = 0; ii < 8; ii++) {
        int i = i0 + ty * 8 + ii;
#pragma unroll
        for (int jj = 0; jj < 4; jj++) {
            out[(size_t)(b * 1024 + i) * 512 + h * 64 + tx * 4 + jj] = acc[ii][jj];
        }
    }
}

extern "C" void kernel_launch(void* const* d_in, const int* in_sizes, int n_in,
                              void* d_out, int out_size) {
    (void)in_sizes; (void)n_in; (void)out_size;
    const float* x_tan = (const float*)d_in[0];
    const float* v_tan = (const float*)d_in[1];
    const float* topo_bias = (const float*)d_in[2];
    const float* qkv_w = (const float*)d_in[3];
    const float* qkv_b = (const float*)d_in[4];
    const float* tau = (const float*)d_in[5];
    const float* topo_gamma = (const float*)d_in[6];

    float* out = (float*)d_out;
    float* zt = out;                               // [4][1024][512]
    float* attn = out + (size_t)NB * NN * ND;      // [4][8][1024][1024]

    float *p_xqkv = nullptr, *p_vqkv = nullptr;
    cudaGetSymbolAddress((void**)&p_xqkv, g_xqkv);
    cudaGetSymbolAddress((void**)&p_vqkv, g_vqkv);

    // topo reachability bitsets (replaces two 1024^3 matmuls)
    pack_kernel<<<1024, 32>>>(topo_bias);
    pow2_kernel<<<1024, 32>>>();
    pow3_kernel<<<1024, 32>>>();

    // QKV projections
    {
        dim3 g(1536 / 64, 4096 / 128);
        gemm_nt<<<g, 256>>>(x_tan, qkv_w, qkv_b, p_xqkv, 512, 1536);
    }
    {
        dim3 g(1024 / 64, 4096 / 128);
        gemm_nt<<<g, 256>>>(v_tan, qkv_w, qkv_b, p_vqkv, 512, 1024);
    }

    // hyperbolic + kinematic feature build
    prep_kernel<<<(32 * 1024) / 8, 256>>>();

    // fused score GEMM (geo + kin + topo) -> attn region
    {
        dim3 g(1024 / 64, 1024 / 128, 32);
        score_kernel<<<g, 256>>>(tau, topo_gamma, attn);
    }

    // softmax in place
    softmax_kernel<<<32 * 1024, 256>>>(attn);

    // z = attn @ v_s
    {
        dim3 g(1, 1024 / 128, 32);
        zgemm_kernel<<<g, 256>>>(attn, zt);
    }
}